// round 1
// baseline (speedup 1.0000x reference)
#include <cuda_runtime.h>
#include <cuda_bf16.h>

#define NB 4
#define NC 64
#define NH 128
#define NW 128
#define NO 64
#define NK2 9
#define NOFF 18
#define NCK 576   // NC * NK2

// Scratch (allocation-free rule: device globals)
__device__ float g_offsets[NB * NOFF * NH * NW];   // (B, 18, H, W)
__device__ float g_wt[NCK * NO];                   // weight transposed: [ck][o]

// ---------------------------------------------------------------------------
// Kernel 0: transpose weight (64, 576) -> g_wt (576, 64). Tiny, one-shot.
// ---------------------------------------------------------------------------
__global__ void transpose_w_kernel(const float* __restrict__ weight) {
    int idx = blockIdx.x * 256 + threadIdx.x;
    if (idx < NO * NCK) {
        int o = idx / NCK;
        int ck = idx - o * NCK;
        g_wt[ck * NO + o] = weight[idx];
    }
}

// ---------------------------------------------------------------------------
// Kernel 1: offset conv.  offsets = conv3x3(x, offset_w, pad=1) + offset_b
// grid (H, B), 128 threads = one output row. 18 accumulators per thread.
// ---------------------------------------------------------------------------
__global__ __launch_bounds__(128) void offsets_kernel(
    const float* __restrict__ x,
    const float* __restrict__ offw,
    const float* __restrict__ offb)
{
    __shared__ __align__(16) float ws[NOFF * NC * 12];  // taps padded 9->12
    int t = threadIdx.x;
    for (int i = t; i < NOFF * NC * 9; i += 128) {
        ws[(i / 9) * 12 + (i % 9)] = offw[i];
    }
    int h = blockIdx.x;
    int b = blockIdx.y;
    int w = t;

    float acc[NOFF];
#pragma unroll
    for (int kk = 0; kk < NOFF; kk++) acc[kk] = __ldg(&offb[kk]);
    __syncthreads();

    const float* xb = x + (size_t)b * NC * NH * NW;
    for (int c = 0; c < NC; c++) {
        const float* xc = xb + c * NH * NW;
        float v[9];
#pragma unroll
        for (int dh = 0; dh < 3; dh++) {
            int hh = h + dh - 1;
#pragma unroll
            for (int dw = 0; dw < 3; dw++) {
                int ww2 = w + dw - 1;
                v[dh * 3 + dw] = (hh >= 0 && hh < NH && ww2 >= 0 && ww2 < NW)
                                   ? __ldg(&xc[hh * NW + ww2]) : 0.f;
            }
        }
#pragma unroll
        for (int kk = 0; kk < NOFF; kk++) {
            const float* wrow = &ws[(kk * NC + c) * 12];
            float4 wa = *(const float4*)(wrow);
            float4 wb = *(const float4*)(wrow + 4);
            float  wc = wrow[8];
            acc[kk] += v[0] * wa.x + v[1] * wa.y + v[2] * wa.z + v[3] * wa.w
                     + v[4] * wb.x + v[5] * wb.y + v[6] * wb.z + v[7] * wb.w
                     + v[8] * wc;
        }
    }
#pragma unroll
    for (int kk = 0; kk < NOFF; kk++)
        g_offsets[((b * NOFF + kk) * NH + h) * NW + w] = acc[kk];
}

// ---------------------------------------------------------------------------
// Kernel 2: fused bilinear sampling + GEMM.
// One block = 32 consecutive pixels of one (b, h) row. 512 threads.
// Shared layout:
//   Ws   [576*64]  = 147456 B   transposed weight, [ck][o]
//   vals [576*32]  =  73728 B   sampled im2col tile, [ck][pixel]
//   prm  [6*288]   =   6912 B   per (pixel,tap) bilinear params
// total 228096 B dynamic smem.
// GEMM: 16 warps, ck-split in halves; warp = 8 output channels x 32 pixels.
// ---------------------------------------------------------------------------
__global__ __launch_bounds__(512) void deform_kernel(
    const float* __restrict__ x,
    const float* __restrict__ bias,
    float* __restrict__ out)
{
    extern __shared__ __align__(16) float smem[];
    float* Ws   = smem;                    // 36864 floats
    float* vals = smem + NCK * NO;         // 18432 floats
    float* prm  = vals + NCK * 32;         // 1728 floats
    int*   ph0  = (int*)prm;               // [288]
    int*   pw0  = ph0 + 288;               // [288]
    float* pwh0 = prm + 576;               // [288]
    float* pwh1 = pwh0 + 288;
    float* pww0 = pwh1 + 288;
    float* pww1 = pww0 + 288;

    int t = threadIdx.x;
    int blk = blockIdx.x;
    int b = blk >> 9;              // 512 tiles per batch
    int tile = blk & 511;
    int h = tile >> 2;
    int wbase = (tile & 3) << 5;

    // Coalesced copy of transposed weight into shared
    for (int i = t; i < NCK * NO; i += 512) Ws[i] = g_wt[i];

    // Per-(pixel, tap) bilinear parameters
    if (t < 288) {
        int p = t & 31;
        int k = t >> 5;          // 0..8
        int w = wbase + p;
        float offh = g_offsets[((b * NOFF + k) * NH + h) * NW + w];
        float offw_ = g_offsets[((b * NOFF + 9 + k) * NH + h) * NW + w];
        float pos_h = (float)(k / 3) + offh + (float)h + 1.f;
        float pos_w = (float)(k % 3) + offw_ + (float)w + 1.f;
        pos_h = fminf(fmaxf(pos_h, 0.f), 129.f);   // padded coords [0, Hp-1]
        pos_w = fminf(fmaxf(pos_w, 0.f), 129.f);
        int h0 = (int)floorf(pos_h);
        int w0 = (int)floorf(pos_w);
        int h1 = min(h0 + 1, 129);
        int w1 = min(w0 + 1, 129);
        ph0 [p * 9 + k] = h0;
        pw0 [p * 9 + k] = w0;
        pwh1[p * 9 + k] = pos_h - (float)h0;
        pwh0[p * 9 + k] = (float)h1 - pos_h;
        pww1[p * 9 + k] = pos_w - (float)w0;
        pww0[p * 9 + k] = (float)w1 - pos_w;
    }
    __syncthreads();

    // Phase A: bilinear sampling -> vals[ck][pixel]
    {
        int p  = t & 31;
        int cg = t >> 5;           // 0..15, channel group
        const float* xb = x + (size_t)b * NC * NH * NW;
        for (int k = 0; k < 9; k++) {
            int h0 = ph0[p * 9 + k];
            int w0 = pw0[p * 9 + k];
            float wh0 = pwh0[p * 9 + k], wh1 = pwh1[p * 9 + k];
            float ww0 = pww0[p * 9 + k], ww1 = pww1[p * 9 + k];
            int ha = h0 - 1, wa = w0 - 1;                 // unpadded coords
            int hb = min(h0 + 1, 129) - 1, wb = min(w0 + 1, 129) - 1;
            bool okha = (unsigned)ha < (unsigned)NH;
            bool okhb = (unsigned)hb < (unsigned)NH;
            bool okwa = (unsigned)wa < (unsigned)NW;
            bool okwb = (unsigned)wb < (unsigned)NW;
            bool ok00 = okha && okwa, ok01 = okha && okwb;
            bool ok10 = okhb && okwa, ok11 = okhb && okwb;
            float f00 = wh0 * ww0, f01 = wh0 * ww1;
            float f10 = wh1 * ww0, f11 = wh1 * ww1;
            int i00 = ha * NW + wa, i01 = ha * NW + wb;
            int i10 = hb * NW + wa, i11 = hb * NW + wb;
#pragma unroll
            for (int cc = 0; cc < 4; cc++) {
                int c = cg + cc * 16;
                const float* xc = xb + c * NH * NW;
                float v00 = ok00 ? __ldg(xc + i00) : 0.f;
                float v01 = ok01 ? __ldg(xc + i01) : 0.f;
                float v10 = ok10 ? __ldg(xc + i10) : 0.f;
                float v11 = ok11 ? __ldg(xc + i11) : 0.f;
                vals[(c * 9 + k) * 32 + p] =
                    v00 * f00 + v01 * f01 + v10 * f10 + v11 * f11;
            }
        }
    }
    __syncthreads();

    // Phase B: GEMM. warp wi: half = wi>>3 picks ck range, (wi&7) picks 8 o's
    int l  = t & 31;
    int wi = t >> 5;
    int half = wi >> 3;
    int og = (wi & 7) << 3;
    float acc[8];
#pragma unroll
    for (int j = 0; j < 8; j++) acc[j] = 0.f;

    int ck0 = half * 288;
    const float* vp = vals + l;
#pragma unroll 4
    for (int ck = ck0; ck < ck0 + 288; ck++) {
        float v = vp[ck * 32];
        float4 w0 = *(const float4*)&Ws[ck * NO + og];
        float4 w1 = *(const float4*)&Ws[ck * NO + og + 4];
        acc[0] += v * w0.x;  acc[1] += v * w0.y;
        acc[2] += v * w0.z;  acc[3] += v * w0.w;
        acc[4] += v * w1.x;  acc[5] += v * w1.y;
        acc[6] += v * w1.z;  acc[7] += v * w1.w;
    }
    __syncthreads();

    // Combine the two ck-halves via shared (reuse vals region)
    float* pbuf = vals;   // 64*32 floats needed
    if (half == 1) {
#pragma unroll
        for (int j = 0; j < 8; j++) pbuf[(og + j) * 32 + l] = acc[j];
    }
    __syncthreads();
    if (half == 0) {
#pragma unroll
        for (int j = 0; j < 8; j++) {
            int o = og + j;
            float r = acc[j] + pbuf[o * 32 + l] + __ldg(&bias[o]);
            out[((b * NO + o) * NH + h) * NW + wbase + l] = r;
        }
    }
}

// ---------------------------------------------------------------------------
extern "C" void kernel_launch(void* const* d_in, const int* in_sizes, int n_in,
                              void* d_out, int out_size) {
    const float* x      = (const float*)d_in[0];
    const float* weight = (const float*)d_in[1];
    const float* bias   = (const float*)d_in[2];
    const float* offw   = (const float*)d_in[3];
    const float* offb   = (const float*)d_in[4];
    float* out = (float*)d_out;

    (void)in_sizes; (void)n_in; (void)out_size;

    cudaFuncSetAttribute(deform_kernel,
                         cudaFuncAttributeMaxDynamicSharedMemorySize, 228096);

    transpose_w_kernel<<<(NO * NCK + 255) / 256, 256>>>(weight);
    offsets_kernel<<<dim3(NH, NB), 128>>>(x, offw, offb);
    deform_kernel<<<NB * NH * NW / 32, 512, 228096>>>(x, bias, out);
}

// round 2
// speedup vs baseline: 1.1895x; 1.1895x over previous
#include <cuda_runtime.h>
#include <cuda_bf16.h>

#define NB 4
#define NC 64
#define NH 128
#define NW 128
#define NO 64
#define NK2 9
#define NOFF 18
#define NCK 576   // NC * NK2

// Scratch (allocation-free rule: device globals)
__device__ float g_offsets[NB * NOFF * NH * NW];   // (B, 18, H, W)
__device__ float g_wt[NCK * NO];                   // weight transposed: [ck][o]
__device__ float g_xt[NB * NH * NW * NC];          // x in NHWC

// ---- packed f32x2 helpers (Blackwell FFMA2 path) ------------------------
__device__ __forceinline__ unsigned long long dup2(float v) {
    unsigned long long r;
    asm("mov.b64 %0, {%1, %1};" : "=l"(r) : "f"(v));
    return r;
}
__device__ __forceinline__ unsigned long long pack2(float lo, float hi) {
    unsigned long long r;
    asm("mov.b64 %0, {%1, %2};" : "=l"(r) : "f"(lo), "f"(hi));
    return r;
}
__device__ __forceinline__ void unpack2(unsigned long long v, float& lo, float& hi) {
    asm("mov.b64 {%0, %1}, %2;" : "=f"(lo), "=f"(hi) : "l"(v));
}
__device__ __forceinline__ void fma2(unsigned long long& d,
                                     unsigned long long a, unsigned long long b) {
    asm("fma.rn.f32x2 %0, %1, %2, %0;" : "+l"(d) : "l"(a), "l"(b));
}
__device__ __forceinline__ unsigned long long add2(unsigned long long a,
                                                   unsigned long long b) {
    unsigned long long r;
    asm("add.rn.f32x2 %0, %1, %2;" : "=l"(r) : "l"(a), "l"(b));
    return r;
}

// ---------------------------------------------------------------------------
// Kernel 0: transpose weight (64, 576) -> g_wt (576, 64). Tiny, one-shot.
// ---------------------------------------------------------------------------
__global__ void transpose_w_kernel(const float* __restrict__ weight) {
    int idx = blockIdx.x * 256 + threadIdx.x;
    if (idx < NO * NCK) {
        int o = idx / NCK;
        int ck = idx - o * NCK;
        g_wt[ck * NO + o] = weight[idx];
    }
}

// ---------------------------------------------------------------------------
// Kernel 0b: NCHW -> NHWC transpose of x via smem tile. block = one (b,h) row.
// ---------------------------------------------------------------------------
__global__ __launch_bounds__(256) void nhwc_kernel(const float* __restrict__ x) {
    __shared__ float ts[NC * 129];
    int bh = blockIdx.x;
    int b = bh >> 7, h = bh & 127;
    int t = threadIdx.x;
    for (int i = t; i < NC * NW; i += 256) {
        int c = i >> 7, w = i & 127;
        ts[c * 129 + w] = x[((size_t)(b * NC + c) * NH + h) * NW + w];
    }
    __syncthreads();
    for (int i = t; i < NC * NW; i += 256) {
        int w = i >> 6, c = i & 63;
        g_xt[(((size_t)(b * NH + h) * NW) + w) * NC + c] = ts[c * 129 + w];
    }
}

// ---------------------------------------------------------------------------
// Kernel 1: offset conv with packed f32x2 accumulation.
// grid (H, B), 128 threads = one output row. 9 f32x2 accumulators (18 ch).
// Shared weights re-laid out as [tap][c][pr-pair], pr padded 9->10 for LDS.128.
// ---------------------------------------------------------------------------
__global__ __launch_bounds__(128) void offsets_kernel(
    const float* __restrict__ x,
    const float* __restrict__ offw,
    const float* __restrict__ offb)
{
    __shared__ __align__(16) float ws2[9 * NC * 10 * 2];  // 46080 B
    int t = threadIdx.x;
    for (int i = t; i < 9 * NC * 10 * 2; i += 128) ws2[i] = 0.f;
    __syncthreads();
    for (int i = t; i < NOFF * NC * 9; i += 128) {
        int kk = i / (NC * 9);
        int rem = i - kk * (NC * 9);
        int c = rem / 9;
        int tap = rem - c * 9;
        ws2[((tap * NC + c) * 10 + (kk >> 1)) * 2 + (kk & 1)] = offw[i];
    }

    int h = blockIdx.x;
    int b = blockIdx.y;
    int w = t;

    unsigned long long acc[9];
#pragma unroll
    for (int j = 0; j < 9; j++) acc[j] = pack2(__ldg(&offb[2 * j]), __ldg(&offb[2 * j + 1]));
    __syncthreads();

    // precompute tap validity + relative indices
    bool ok9[9];
    int idx9[9];
#pragma unroll
    for (int dh = 0; dh < 3; dh++)
#pragma unroll
        for (int dw = 0; dw < 3; dw++) {
            int hh = h + dh - 1, ww2 = w + dw - 1;
            ok9[dh * 3 + dw] = (hh >= 0 && hh < NH && ww2 >= 0 && ww2 < NW);
            idx9[dh * 3 + dw] = hh * NW + ww2;
        }

    const float* xb = x + (size_t)b * NC * NH * NW;
    for (int c = 0; c < NC; c++) {
        const float* xc = xb + c * NH * NW;
        float v[9];
#pragma unroll
        for (int k = 0; k < 9; k++) v[k] = ok9[k] ? __ldg(&xc[idx9[k]]) : 0.f;
#pragma unroll
        for (int tap = 0; tap < 9; tap++) {
            unsigned long long vd = dup2(v[tap]);
            const ulonglong2* wq = (const ulonglong2*)&ws2[(tap * NC + c) * 20];
            ulonglong2 q0 = wq[0], q1 = wq[1], q2 = wq[2], q3 = wq[3], q4 = wq[4];
            fma2(acc[0], vd, q0.x); fma2(acc[1], vd, q0.y);
            fma2(acc[2], vd, q1.x); fma2(acc[3], vd, q1.y);
            fma2(acc[4], vd, q2.x); fma2(acc[5], vd, q2.y);
            fma2(acc[6], vd, q3.x); fma2(acc[7], vd, q3.y);
            fma2(acc[8], vd, q4.x);
        }
    }
#pragma unroll
    for (int j = 0; j < 9; j++) {
        float lo, hi;
        unpack2(acc[j], lo, hi);
        g_offsets[((b * NOFF + 2 * j) * NH + h) * NW + w] = lo;
        g_offsets[((b * NOFF + 2 * j + 1) * NH + h) * NW + w] = hi;
    }
}

// ---------------------------------------------------------------------------
// Kernel 2: persistent fused bilinear sampling + GEMM.
// grid = #SMs, 512 threads, 1 block/SM (228224 B smem). Each block loops tiles.
// Tile = 32 consecutive pixels of one (b,h) row.
// Shared:
//   Ws   [576*64]     147456 B   (loaded once per block)
//   vals [32*577]      73856 B   im2col tile, [p][ck], pad 577 (conflict-free)
//   prm  [6*288]        6912 B
// GEMM: 16 warps = 4 ck-groups x 4 o-groups of 16; f32x2 accumulators.
// ---------------------------------------------------------------------------
#define NTILES (NB * NH * NW / 32)   // 2048

__global__ __launch_bounds__(512) void deform_kernel(
    const float* __restrict__ xt,
    const float* __restrict__ bias,
    float* __restrict__ out)
{
    extern __shared__ __align__(16) float smem[];
    float* Ws = smem;                    // 36864 floats
    float* vals = smem + NCK * NO;       // 18464 floats (32*577)
    float* prm = vals + 32 * 577;        // 1728 floats
    int* ph0 = (int*)prm;                // [288]
    int* pw0 = ph0 + 288;
    float* pwh0 = prm + 576;
    float* pwh1 = pwh0 + 288;
    float* pww0 = pwh1 + 288;
    float* pww1 = pww0 + 288;

    int t = threadIdx.x;
    int l = t & 31;
    int wi = t >> 5;

    // Load transposed weight once (coalesced)
    for (int i = t; i < NCK * NO; i += 512) Ws[i] = g_wt[i];

    for (int tile = blockIdx.x; tile < NTILES; tile += gridDim.x) {
        int b = tile >> 9;
        int h = (tile >> 2) & 127;
        int wbase = (tile & 3) << 5;

        __syncthreads();   // previous-iteration consumers done with vals/prm

        // ---- bilinear params, one thread per (pixel, tap) ----
        if (t < 288) {
            int p = t / 9;
            int k = t - p * 9;
            int w = wbase + p;
            float offh = g_offsets[((b * NOFF + k) * NH + h) * NW + w];
            float offw_ = g_offsets[((b * NOFF + 9 + k) * NH + h) * NW + w];
            float pos_h = (float)(k / 3) + offh + (float)h + 1.f;
            float pos_w = (float)(k % 3) + offw_ + (float)w + 1.f;
            pos_h = fminf(fmaxf(pos_h, 0.f), 129.f);
            pos_w = fminf(fmaxf(pos_w, 0.f), 129.f);
            int h0 = (int)floorf(pos_h);
            int w0 = (int)floorf(pos_w);
            int h1 = min(h0 + 1, 129);
            int w1 = min(w0 + 1, 129);
            ph0[t] = h0;
            pw0[t] = w0;
            pwh1[t] = pos_h - (float)h0;
            pwh0[t] = (float)h1 - pos_h;
            pww1[t] = pos_w - (float)w0;
            pww0[t] = (float)w1 - pos_w;
        }
        __syncthreads();

        // ---- Phase A: NHWC coalesced gather. warp <-> (pixel,tap) pair ----
        {
            const float* xb = xt + (size_t)b * NH * NW * NC;
#pragma unroll 2
            for (int it = 0; it < 18; it++) {
                int idx = it * 16 + wi;     // 0..287
                int p = idx / 9;
                int k = idx - p * 9;
                int h0 = ph0[idx], w0 = pw0[idx];
                float wh0 = pwh0[idx], wh1 = pwh1[idx];
                float ww0 = pww0[idx], ww1 = pww1[idx];
                float f00 = wh0 * ww0, f01 = wh0 * ww1;
                float f10 = wh1 * ww0, f11 = wh1 * ww1;
                int ha = h0 - 1, wa = w0 - 1;
                int hb = min(h0 + 1, 129) - 1, wb = min(w0 + 1, 129) - 1;
                bool okha = (unsigned)ha < (unsigned)NH;
                bool okhb = (unsigned)hb < (unsigned)NH;
                bool okwa = (unsigned)wa < (unsigned)NW;
                bool okwb = (unsigned)wb < (unsigned)NW;
                bool ok00 = okha && okwa, ok01 = okha && okwb;
                bool ok10 = okhb && okwa, ok11 = okhb && okwb;
                const float* p00 = xb + (size_t)(ha * NW + wa) * NC;
                const float* p01 = xb + (size_t)(ha * NW + wb) * NC;
                const float* p10 = xb + (size_t)(hb * NW + wa) * NC;
                const float* p11 = xb + (size_t)(hb * NW + wb) * NC;
                float v00a = ok00 ? __ldg(p00 + l) : 0.f;
                float v01a = ok01 ? __ldg(p01 + l) : 0.f;
                float v10a = ok10 ? __ldg(p10 + l) : 0.f;
                float v11a = ok11 ? __ldg(p11 + l) : 0.f;
                float v00b = ok00 ? __ldg(p00 + l + 32) : 0.f;
                float v01b = ok01 ? __ldg(p01 + l + 32) : 0.f;
                float v10b = ok10 ? __ldg(p10 + l + 32) : 0.f;
                float v11b = ok11 ? __ldg(p11 + l + 32) : 0.f;
                float va = v00a * f00 + v01a * f01 + v10a * f10 + v11a * f11;
                float vb = v00b * f00 + v01b * f01 + v10b * f10 + v11b * f11;
                vals[p * 577 + 9 * l + k] = va;          // bank 9l : conflict-free
                vals[p * 577 + 9 * (l + 32) + k] = vb;
            }
        }
        __syncthreads();

        // ---- Phase B: GEMM, f32x2. warp = 16 o x 32 px, 4-way ck split ----
        int ckg = wi >> 2;
        int og = (wi & 3) << 4;
        unsigned long long acc[8];
#pragma unroll
        for (int j = 0; j < 8; j++) acc[j] = 0ull;

        const float* vp = vals + l * 577 + ckg * 144;
        const float* wsp = Ws + (ckg * 144) * NO + og;
#pragma unroll 4
        for (int ck = 0; ck < 144; ck++) {
            unsigned long long vd = dup2(vp[ck]);
            const ulonglong2* wq = (const ulonglong2*)(wsp + ck * NO);
            ulonglong2 q0 = wq[0], q1 = wq[1], q2 = wq[2], q3 = wq[3];
            fma2(acc[0], vd, q0.x); fma2(acc[1], vd, q0.y);
            fma2(acc[2], vd, q1.x); fma2(acc[3], vd, q1.y);
            fma2(acc[4], vd, q2.x); fma2(acc[5], vd, q2.y);
            fma2(acc[6], vd, q3.x); fma2(acc[7], vd, q3.y);
        }
        __syncthreads();   // vals consumed; safe to reuse as pbuf

        float* pbuf = vals;   // 3 groups x 32 px x 66 floats
        if (ckg > 0) {
#pragma unroll
            for (int j = 0; j < 8; j++)
                *(unsigned long long*)&pbuf[(ckg - 1) * 2112 + l * 66 + og + 2 * j] = acc[j];
        }
        __syncthreads();

        if (ckg == 0) {
#pragma unroll
            for (int j = 0; j < 8; j++) {
                unsigned long long s = acc[j];
                s = add2(s, *(const unsigned long long*)&pbuf[0 * 2112 + l * 66 + og + 2 * j]);
                s = add2(s, *(const unsigned long long*)&pbuf[1 * 2112 + l * 66 + og + 2 * j]);
                s = add2(s, *(const unsigned long long*)&pbuf[2 * 2112 + l * 66 + og + 2 * j]);
                float lo, hi;
                unpack2(s, lo, hi);
                int o = og + 2 * j;
                out[((b * NO + o) * NH + h) * NW + wbase + l] = lo + __ldg(&bias[o]);
                out[((b * NO + o + 1) * NH + h) * NW + wbase + l] = hi + __ldg(&bias[o + 1]);
            }
        }
    }
}

// ---------------------------------------------------------------------------
extern "C" void kernel_launch(void* const* d_in, const int* in_sizes, int n_in,
                              void* d_out, int out_size) {
    const float* x      = (const float*)d_in[0];
    const float* weight = (const float*)d_in[1];
    const float* bias   = (const float*)d_in[2];
    const float* offw   = (const float*)d_in[3];
    const float* offb   = (const float*)d_in[4];
    float* out = (float*)d_out;

    (void)in_sizes; (void)n_in; (void)out_size;

    cudaFuncSetAttribute(deform_kernel,
                         cudaFuncAttributeMaxDynamicSharedMemorySize, 228224);

    transpose_w_kernel<<<(NO * NCK + 255) / 256, 256>>>(weight);
    nhwc_kernel<<<NB * NH, 256>>>(x);
    offsets_kernel<<<dim3(NH, NB), 128>>>(x, offw, offb);

    float* xt;
    cudaGetSymbolAddress((void**)&xt, g_xt);
    deform_kernel<<<152, 512, 228224>>>(xt, bias, out);
}

// round 3
// speedup vs baseline: 1.3106x; 1.1018x over previous
#include <cuda_runtime.h>
#include <cuda_bf16.h>

#define NB 4
#define NC 64
#define NH 128
#define NW 128
#define NO 64
#define NK2 9
#define NOFF 18
#define NCK 576   // NC * NK2

// Scratch (allocation-free rule: device globals)
__device__ float g_offsets[NB * NOFF * NH * NW];   // (B, 18, H, W)
__device__ float g_wt[NCK * NO];                   // weight transposed: [ck][o]
__device__ float g_xt[NB * NH * NW * NC];          // x in NHWC

// ---- packed f32x2 helpers (Blackwell FFMA2 path) ------------------------
__device__ __forceinline__ unsigned long long dup2(float v) {
    unsigned long long r;
    asm("mov.b64 %0, {%1, %1};" : "=l"(r) : "f"(v));
    return r;
}
__device__ __forceinline__ unsigned long long pack2(float lo, float hi) {
    unsigned long long r;
    asm("mov.b64 %0, {%1, %2};" : "=l"(r) : "f"(lo), "f"(hi));
    return r;
}
__device__ __forceinline__ void unpack2(unsigned long long v, float& lo, float& hi) {
    asm("mov.b64 {%0, %1}, %2;" : "=f"(lo), "=f"(hi) : "l"(v));
}
__device__ __forceinline__ void fma2(unsigned long long& d,
                                     unsigned long long a, unsigned long long b) {
    asm("fma.rn.f32x2 %0, %1, %2, %0;" : "+l"(d) : "l"(a), "l"(b));
}
__device__ __forceinline__ unsigned long long add2(unsigned long long a,
                                                   unsigned long long b) {
    unsigned long long r;
    asm("add.rn.f32x2 %0, %1, %2;" : "=l"(r) : "l"(a), "l"(b));
    return r;
}

// ---------------------------------------------------------------------------
// Kernel 0: transpose weight (64, 576) -> g_wt (576, 64). Tiny, one-shot.
// ---------------------------------------------------------------------------
__global__ void transpose_w_kernel(const float* __restrict__ weight) {
    int idx = blockIdx.x * 256 + threadIdx.x;
    if (idx < NO * NCK) {
        int o = idx / NCK;
        int ck = idx - o * NCK;
        g_wt[ck * NO + o] = weight[idx];
    }
}

// ---------------------------------------------------------------------------
// Kernel 0b: NCHW -> NHWC transpose of x via smem tile. block = one (b,h) row.
// ---------------------------------------------------------------------------
__global__ __launch_bounds__(256) void nhwc_kernel(const float* __restrict__ x) {
    __shared__ float ts[NC * 129];
    int bh = blockIdx.x;
    int b = bh >> 7, h = bh & 127;
    int t = threadIdx.x;
    for (int i = t; i < NC * NW; i += 256) {
        int c = i >> 7, w = i & 127;
        ts[c * 129 + w] = x[((size_t)(b * NC + c) * NH + h) * NW + w];
    }
    __syncthreads();
    for (int i = t; i < NC * NW; i += 256) {
        int w = i >> 6, c = i & 63;
        g_xt[(((size_t)(b * NH + h) * NW) + w) * NC + c] = ts[c * 129 + w];
    }
}

// ---------------------------------------------------------------------------
// Kernel 1: offset conv with packed f32x2 accumulation.
// grid (H, B), 128 threads = one output row. 9 f32x2 accumulators (18 ch).
// ---------------------------------------------------------------------------
__global__ __launch_bounds__(128) void offsets_kernel(
    const float* __restrict__ x,
    const float* __restrict__ offw,
    const float* __restrict__ offb)
{
    __shared__ __align__(16) float ws2[9 * NC * 10 * 2];  // 46080 B
    int t = threadIdx.x;
    for (int i = t; i < 9 * NC * 10 * 2; i += 128) ws2[i] = 0.f;
    __syncthreads();
    for (int i = t; i < NOFF * NC * 9; i += 128) {
        int kk = i / (NC * 9);
        int rem = i - kk * (NC * 9);
        int c = rem / 9;
        int tap = rem - c * 9;
        ws2[((tap * NC + c) * 10 + (kk >> 1)) * 2 + (kk & 1)] = offw[i];
    }

    int h = blockIdx.x;
    int b = blockIdx.y;
    int w = t;

    unsigned long long acc[9];
#pragma unroll
    for (int j = 0; j < 9; j++) acc[j] = pack2(__ldg(&offb[2 * j]), __ldg(&offb[2 * j + 1]));
    __syncthreads();

    bool ok9[9];
    int idx9[9];
#pragma unroll
    for (int dh = 0; dh < 3; dh++)
#pragma unroll
        for (int dw = 0; dw < 3; dw++) {
            int hh = h + dh - 1, ww2 = w + dw - 1;
            ok9[dh * 3 + dw] = (hh >= 0 && hh < NH && ww2 >= 0 && ww2 < NW);
            idx9[dh * 3 + dw] = hh * NW + ww2;
        }

    const float* xb = x + (size_t)b * NC * NH * NW;
    for (int c = 0; c < NC; c++) {
        const float* xc = xb + c * NH * NW;
        float v[9];
#pragma unroll
        for (int k = 0; k < 9; k++) v[k] = ok9[k] ? __ldg(&xc[idx9[k]]) : 0.f;
#pragma unroll
        for (int tap = 0; tap < 9; tap++) {
            unsigned long long vd = dup2(v[tap]);
            const ulonglong2* wq = (const ulonglong2*)&ws2[(tap * NC + c) * 20];
            ulonglong2 q0 = wq[0], q1 = wq[1], q2 = wq[2], q3 = wq[3], q4 = wq[4];
            fma2(acc[0], vd, q0.x); fma2(acc[1], vd, q0.y);
            fma2(acc[2], vd, q1.x); fma2(acc[3], vd, q1.y);
            fma2(acc[4], vd, q2.x); fma2(acc[5], vd, q2.y);
            fma2(acc[6], vd, q3.x); fma2(acc[7], vd, q3.y);
            fma2(acc[8], vd, q4.x);
        }
    }
#pragma unroll
    for (int j = 0; j < 9; j++) {
        float lo, hi;
        unpack2(acc[j], lo, hi);
        g_offsets[((b * NOFF + 2 * j) * NH + h) * NW + w] = lo;
        g_offsets[((b * NOFF + 2 * j + 1) * NH + h) * NW + w] = hi;
    }
}

// ---------------------------------------------------------------------------
// Kernel 2: persistent fused bilinear sampling + GEMM.
// grid = #SMs, 1024 threads (32 warps), 1 block/SM (228224 B smem).
// Tile = 32 consecutive pixels of one (b,h) row.
// Shared:
//   Ws   [576*64]     147456 B   (loaded once per block)
//   vals [32*577]      73856 B   im2col tile, [p][ck], pad 577 (conflict-free)
//   prm  [6*288]        6912 B
// GEMM: 32 warps = 8 ck-groups (72 ck) x 4 o-groups (16 o); f32x2 accumulators.
// ---------------------------------------------------------------------------
#define NTILES (NB * NH * NW / 32)   // 2048

__global__ __launch_bounds__(1024) void deform_kernel(
    const float* __restrict__ xt,
    const float* __restrict__ bias,
    float* __restrict__ out)
{
    extern __shared__ __align__(16) float smem[];
    float* Ws = smem;                    // 36864 floats
    float* vals = smem + NCK * NO;       // 18464 floats (32*577)
    float* prm = vals + 32 * 577;        // 1728 floats
    int* ph0 = (int*)prm;                // [288]
    int* pw0 = ph0 + 288;
    float* pwh0 = prm + 576;
    float* pwh1 = pwh0 + 288;
    float* pww0 = pwh1 + 288;
    float* pww1 = pww0 + 288;

    int t = threadIdx.x;
    int l = t & 31;
    int wi = t >> 5;            // 0..31

    // Load transposed weight once (coalesced)
    for (int i = t; i < NCK * NO; i += 1024) Ws[i] = g_wt[i];

    for (int tile = blockIdx.x; tile < NTILES; tile += gridDim.x) {
        int b = tile >> 9;
        int h = (tile >> 2) & 127;
        int wbase = (tile & 3) << 5;

        __syncthreads();   // previous-iteration consumers done with vals/prm

        // ---- bilinear params, one thread per (pixel, tap) ----
        if (t < 288) {
            int p = t / 9;
            int k = t - p * 9;
            int w = wbase + p;
            float offh = g_offsets[((b * NOFF + k) * NH + h) * NW + w];
            float offw_ = g_offsets[((b * NOFF + 9 + k) * NH + h) * NW + w];
            float pos_h = (float)(k / 3) + offh + (float)h + 1.f;
            float pos_w = (float)(k % 3) + offw_ + (float)w + 1.f;
            pos_h = fminf(fmaxf(pos_h, 0.f), 129.f);
            pos_w = fminf(fmaxf(pos_w, 0.f), 129.f);
            int h0 = (int)floorf(pos_h);
            int w0 = (int)floorf(pos_w);
            int h1 = min(h0 + 1, 129);
            int w1 = min(w0 + 1, 129);
            ph0[t] = h0;
            pw0[t] = w0;
            pwh1[t] = pos_h - (float)h0;
            pwh0[t] = (float)h1 - pos_h;
            pww1[t] = pos_w - (float)w0;
            pww0[t] = (float)w1 - pos_w;
        }
        __syncthreads();

        // ---- Phase A: NHWC coalesced gather. warp <-> (pixel,tap) pair ----
        {
            const float* xb = xt + (size_t)b * NH * NW * NC;
#pragma unroll 3
            for (int it = 0; it < 9; it++) {
                int idx = it * 32 + wi;     // 0..287
                int p = idx / 9;
                int k = idx - p * 9;
                int h0 = ph0[idx], w0 = pw0[idx];
                float wh0 = pwh0[idx], wh1 = pwh1[idx];
                float ww0 = pww0[idx], ww1 = pww1[idx];
                float f00 = wh0 * ww0, f01 = wh0 * ww1;
                float f10 = wh1 * ww0, f11 = wh1 * ww1;
                int ha = h0 - 1, wa = w0 - 1;
                int hb = min(h0 + 1, 129) - 1, wb = min(w0 + 1, 129) - 1;
                bool okha = (unsigned)ha < (unsigned)NH;
                bool okhb = (unsigned)hb < (unsigned)NH;
                bool okwa = (unsigned)wa < (unsigned)NW;
                bool okwb = (unsigned)wb < (unsigned)NW;
                bool ok00 = okha && okwa, ok01 = okha && okwb;
                bool ok10 = okhb && okwa, ok11 = okhb && okwb;
                const float* p00 = xb + (size_t)(ha * NW + wa) * NC;
                const float* p01 = xb + (size_t)(ha * NW + wb) * NC;
                const float* p10 = xb + (size_t)(hb * NW + wa) * NC;
                const float* p11 = xb + (size_t)(hb * NW + wb) * NC;
                float v00a = ok00 ? __ldg(p00 + l) : 0.f;
                float v01a = ok01 ? __ldg(p01 + l) : 0.f;
                float v10a = ok10 ? __ldg(p10 + l) : 0.f;
                float v11a = ok11 ? __ldg(p11 + l) : 0.f;
                float v00b = ok00 ? __ldg(p00 + l + 32) : 0.f;
                float v01b = ok01 ? __ldg(p01 + l + 32) : 0.f;
                float v10b = ok10 ? __ldg(p10 + l + 32) : 0.f;
                float v11b = ok11 ? __ldg(p11 + l + 32) : 0.f;
                float va = v00a * f00 + v01a * f01 + v10a * f10 + v11a * f11;
                float vb = v00b * f00 + v01b * f01 + v10b * f10 + v11b * f11;
                vals[p * 577 + 9 * l + k] = va;          // bank 9l : conflict-free
                vals[p * 577 + 9 * (l + 32) + k] = vb;
            }
        }
        __syncthreads();

        // ---- Phase B: GEMM, f32x2. warp = 16 o x 32 px, 8-way ck split ----
        int ckg = wi >> 2;              // 0..7  (72 ck each)
        int og = (wi & 3) << 4;         // 0,16,32,48
        unsigned long long acc[8];
#pragma unroll
        for (int j = 0; j < 8; j++) acc[j] = 0ull;

        const float* vp = vals + l * 577 + ckg * 72;
        const float* wsp = Ws + (ckg * 72) * NO + og;
#pragma unroll 4
        for (int ck = 0; ck < 72; ck++) {
            unsigned long long vd = dup2(vp[ck]);
            const ulonglong2* wq = (const ulonglong2*)(wsp + ck * NO);
            ulonglong2 q0 = wq[0], q1 = wq[1], q2 = wq[2], q3 = wq[3];
            fma2(acc[0], vd, q0.x); fma2(acc[1], vd, q0.y);
            fma2(acc[2], vd, q1.x); fma2(acc[3], vd, q1.y);
            fma2(acc[4], vd, q2.x); fma2(acc[5], vd, q2.y);
            fma2(acc[6], vd, q3.x); fma2(acc[7], vd, q3.y);
        }
        __syncthreads();   // vals consumed; safe to reuse as pbuf

        // Partial reduction: groups 1..7 write, group 0 combines.
        float* pbuf = vals;   // 7 groups x 32 px x 66 floats = 14784 floats
        if (ckg > 0) {
#pragma unroll
            for (int j = 0; j < 8; j++)
                *(unsigned long long*)&pbuf[(ckg - 1) * 2112 + l * 66 + og + 2 * j] = acc[j];
        }
        __syncthreads();

        if (ckg == 0) {
#pragma unroll
            for (int j = 0; j < 8; j++) {
                unsigned long long s = acc[j];
#pragma unroll
                for (int g = 0; g < 7; g++)
                    s = add2(s, *(const unsigned long long*)&pbuf[g * 2112 + l * 66 + og + 2 * j]);
                float lo, hi;
                unpack2(s, lo, hi);
                int o = og + 2 * j;
                out[((b * NO + o) * NH + h) * NW + wbase + l] = lo + __ldg(&bias[o]);
                out[((b * NO + o + 1) * NH + h) * NW + wbase + l] = hi + __ldg(&bias[o + 1]);
            }
        }
    }
}

// ---------------------------------------------------------------------------
extern "C" void kernel_launch(void* const* d_in, const int* in_sizes, int n_in,
                              void* d_out, int out_size) {
    const float* x      = (const float*)d_in[0];
    const float* weight = (const float*)d_in[1];
    const float* bias   = (const float*)d_in[2];
    const float* offw   = (const float*)d_in[3];
    const float* offb   = (const float*)d_in[4];
    float* out = (float*)d_out;

    (void)in_sizes; (void)n_in; (void)out_size;

    cudaFuncSetAttribute(deform_kernel,
                         cudaFuncAttributeMaxDynamicSharedMemorySize, 228224);

    transpose_w_kernel<<<(NO * NCK + 255) / 256, 256>>>(weight);
    nhwc_kernel<<<NB * NH, 256>>>(x);
    offsets_kernel<<<dim3(NH, NB), 128>>>(x, offw, offb);

    float* xt;
    cudaGetSymbolAddress((void**)&xt, g_xt);
    deform_kernel<<<152, 1024, 228224>>>(xt, bias, out);
}

// round 4
// speedup vs baseline: 1.5564x; 1.1876x over previous
#include <cuda_runtime.h>
#include <cuda_bf16.h>

#define NB 4
#define NC 64
#define NH 128
#define NW 128
#define NO 64
#define NK2 9
#define NOFF 18
#define NCK 576   // NC * NK2
#define HWSZ (NH * NW)

// Scratch (allocation-free rule: device globals)
__device__ float g_offsets[NB * NOFF * NH * NW];   // (B, 18, H, W)
__device__ float g_wt[NCK * NO];                   // weight transposed: [ck][o]

// ---- packed f32x2 helpers (Blackwell FFMA2 path) ------------------------
__device__ __forceinline__ unsigned long long dup2(float v) {
    unsigned long long r;
    asm("mov.b64 %0, {%1, %1};" : "=l"(r) : "f"(v));
    return r;
}
__device__ __forceinline__ unsigned long long pack2(float lo, float hi) {
    unsigned long long r;
    asm("mov.b64 %0, {%1, %2};" : "=l"(r) : "f"(lo), "f"(hi));
    return r;
}
__device__ __forceinline__ void unpack2(unsigned long long v, float& lo, float& hi) {
    asm("mov.b64 {%0, %1}, %2;" : "=f"(lo), "=f"(hi) : "l"(v));
}
__device__ __forceinline__ void fma2(unsigned long long& d,
                                     unsigned long long a, unsigned long long b) {
    asm("fma.rn.f32x2 %0, %1, %2, %0;" : "+l"(d) : "l"(a), "l"(b));
}

// ---------------------------------------------------------------------------
// Kernel 0: transpose weight (64, 576) -> g_wt (576, 64). Tiny, one-shot.
// ---------------------------------------------------------------------------
__global__ void transpose_w_kernel(const float* __restrict__ weight) {
    int idx = blockIdx.x * 256 + threadIdx.x;
    if (idx < NO * NCK) {
        int o = idx / NCK;
        int ck = idx - o * NCK;
        g_wt[ck * NO + o] = weight[idx];
    }
}

// ---------------------------------------------------------------------------
// Kernel 1: offset conv with packed f32x2 accumulation.
// grid (H, B), 128 threads = one output row. 9 f32x2 accumulators (18 ch).
// ---------------------------------------------------------------------------
__global__ __launch_bounds__(128) void offsets_kernel(
    const float* __restrict__ x,
    const float* __restrict__ offw,
    const float* __restrict__ offb)
{
    __shared__ __align__(16) float ws2[9 * NC * 10 * 2];  // 46080 B
    int t = threadIdx.x;
    for (int i = t; i < 9 * NC * 10 * 2; i += 128) ws2[i] = 0.f;
    __syncthreads();
    for (int i = t; i < NOFF * NC * 9; i += 128) {
        int kk = i / (NC * 9);
        int rem = i - kk * (NC * 9);
        int c = rem / 9;
        int tap = rem - c * 9;
        ws2[((tap * NC + c) * 10 + (kk >> 1)) * 2 + (kk & 1)] = offw[i];
    }

    int h = blockIdx.x;
    int b = blockIdx.y;
    int w = t;

    unsigned long long acc[9];
#pragma unroll
    for (int j = 0; j < 9; j++) acc[j] = pack2(__ldg(&offb[2 * j]), __ldg(&offb[2 * j + 1]));
    __syncthreads();

    bool ok9[9];
    int idx9[9];
#pragma unroll
    for (int dh = 0; dh < 3; dh++)
#pragma unroll
        for (int dw = 0; dw < 3; dw++) {
            int hh = h + dh - 1, ww2 = w + dw - 1;
            ok9[dh * 3 + dw] = (hh >= 0 && hh < NH && ww2 >= 0 && ww2 < NW);
            idx9[dh * 3 + dw] = hh * NW + ww2;
        }

    const float* xb = x + (size_t)b * NC * NH * NW;
    for (int c = 0; c < NC; c++) {
        const float* xc = xb + c * HWSZ;
        float v[9];
#pragma unroll
        for (int k = 0; k < 9; k++) v[k] = ok9[k] ? __ldg(&xc[idx9[k]]) : 0.f;
#pragma unroll
        for (int tap = 0; tap < 9; tap++) {
            unsigned long long vd = dup2(v[tap]);
            const ulonglong2* wq = (const ulonglong2*)&ws2[(tap * NC + c) * 20];
            ulonglong2 q0 = wq[0], q1 = wq[1], q2 = wq[2], q3 = wq[3], q4 = wq[4];
            fma2(acc[0], vd, q0.x); fma2(acc[1], vd, q0.y);
            fma2(acc[2], vd, q1.x); fma2(acc[3], vd, q1.y);
            fma2(acc[4], vd, q2.x); fma2(acc[5], vd, q2.y);
            fma2(acc[6], vd, q3.x); fma2(acc[7], vd, q3.y);
            fma2(acc[8], vd, q4.x);
        }
    }
#pragma unroll
    for (int j = 0; j < 9; j++) {
        float lo, hi;
        unpack2(acc[j], lo, hi);
        g_offsets[((b * NOFF + 2 * j) * NH + h) * NW + w] = lo;
        g_offsets[((b * NOFF + 2 * j + 1) * NH + h) * NW + w] = hi;
    }
}

// ---------------------------------------------------------------------------
// Kernel 2: persistent fused bilinear sampling + GEMM, 2D register tiling.
// grid = 152, 512 threads (16 warps), 1 block/SM.
// Tile = 32 consecutive pixels of one (b,h) row.
// Shared (230400 B):
//   Ws   [576][64]   147456 B   weights, 256 B rows (loaded once)
//   vals [576][32]    73728 B   im2col, 128 B rows, px-major (conflict-free)
//   prm  8 x [288]     9216 B   folded bilinear params (f==0 for invalid)
// GEMM: warp = 32 px x 32 o; thread = 8 px x 4 o; 8-way ck split, 2 o-halves.
// ---------------------------------------------------------------------------
#define NTILES (NB * NH * NW / 32)   // 2048
#define SMEM_BYTES 230400

__global__ __launch_bounds__(512, 1) void deform_kernel(
    const float* __restrict__ x,
    const float* __restrict__ bias,
    float* __restrict__ out)
{
    extern __shared__ __align__(16) float smem[];
    float* Ws   = smem;                  // 36864 floats
    float* vals = smem + NCK * NO;       // 18432 floats
    float* prm  = vals + NCK * 32;       // 2304 floats
    float* pf00 = prm;
    float* pf01 = prm + 288;
    float* pf10 = prm + 576;
    float* pf11 = prm + 864;
    int*   pi00 = (int*)(prm + 1152);
    int*   pi01 = (int*)(prm + 1440);
    int*   pi10 = (int*)(prm + 1728);
    int*   pi11 = (int*)(prm + 2016);

    int t  = threadIdx.x;
    int l  = t & 31;
    int wi = t >> 5;            // 0..15
    int ckg = wi >> 1;          // 0..7   (72 ck each)
    int oh  = wi & 1;           // o half
    int og  = l >> 2;           // 0..7
    int pxg = l & 3;            // 0..3
    int o_base = oh * 32 + og * 4;

    // Load transposed weight once (coalesced)
    for (int i = t; i < NCK * NO; i += 512) Ws[i] = g_wt[i];

    for (int tile = blockIdx.x; tile < NTILES; tile += gridDim.x) {
        int b = tile >> 9;
        int h = (tile >> 2) & 127;
        int wbase = (tile & 3) << 5;

        __syncthreads();   // previous-iteration consumers done with vals/prm

        // ---- bilinear params: t<288, k = t>>5, px = t&31; fold masks ----
        if (t < 288) {
            int k = t >> 5;
            int p = t & 31;
            int w = wbase + p;
            float offh  = g_offsets[((b * NOFF + k) * NH + h) * NW + w];
            float offw_ = g_offsets[((b * NOFF + 9 + k) * NH + h) * NW + w];
            float pos_h = (float)(k / 3) + offh + (float)h + 1.f;
            float pos_w = (float)(k % 3) + offw_ + (float)w + 1.f;
            pos_h = fminf(fmaxf(pos_h, 0.f), 129.f);
            pos_w = fminf(fmaxf(pos_w, 0.f), 129.f);
            int h0 = (int)floorf(pos_h);
            int w0 = (int)floorf(pos_w);
            int h1 = min(h0 + 1, 129);
            int w1 = min(w0 + 1, 129);
            float wh1 = pos_h - (float)h0;
            float wh0 = (float)h1 - pos_h;
            float ww1 = pos_w - (float)w0;
            float ww0 = (float)w1 - pos_w;
            // unpadded coords
            int ha = h0 - 1, wa = w0 - 1;
            int hb = h1 - 1, wb = w1 - 1;
            bool okha = (unsigned)ha < (unsigned)NH;
            bool okhb = (unsigned)hb < (unsigned)NH;
            bool okwa = (unsigned)wa < (unsigned)NW;
            bool okwb = (unsigned)wb < (unsigned)NW;
            bool ok00 = okha && okwa, ok01 = okha && okwb;
            bool ok10 = okhb && okwa, ok11 = okhb && okwb;
            pf00[t] = ok00 ? wh0 * ww0 : 0.f;
            pf01[t] = ok01 ? wh0 * ww1 : 0.f;
            pf10[t] = ok10 ? wh1 * ww0 : 0.f;
            pf11[t] = ok11 ? wh1 * ww1 : 0.f;
            pi00[t] = ok00 ? ha * NW + wa : 0;
            pi01[t] = ok01 ? ha * NW + wb : 0;
            pi10[t] = ok10 ? hb * NW + wa : 0;
            pi11[t] = ok11 ? hb * NW + wb : 0;
        }
        __syncthreads();

        // ---- Phase A: lane = pixel, warp = 4 channels x 9 taps ----
        {
            int c4 = wi * 4;
            const float* xb = x + (size_t)b * NC * HWSZ;
#pragma unroll
            for (int k = 0; k < 9; k++) {
                int base = k * 32 + l;
                float f00 = pf00[base], f01 = pf01[base];
                float f10 = pf10[base], f11 = pf11[base];
                int i00 = pi00[base], i01 = pi01[base];
                int i10 = pi10[base], i11 = pi11[base];
#pragma unroll
                for (int cc = 0; cc < 4; cc++) {
                    const float* xc = xb + (c4 + cc) * HWSZ;
                    float v = __ldg(xc + i00) * f00 + __ldg(xc + i01) * f01
                            + __ldg(xc + i10) * f10 + __ldg(xc + i11) * f11;
                    vals[((c4 + cc) * 9 + k) * 32 + l] = v;   // bank = l: CF
                }
            }
        }
        __syncthreads();

        // ---- Phase B: GEMM, thread = 8px x 4o, f32x2 ----
        unsigned long long acc[4][4];
#pragma unroll
        for (int i = 0; i < 4; i++)
#pragma unroll
            for (int j = 0; j < 4; j++) acc[i][j] = 0ull;

        {
            const float* vbase = vals + pxg * 8;
            const float* wbaseP = Ws + o_base;
            int ck0 = ckg * 72;
#pragma unroll 2
            for (int ck = ck0; ck < ck0 + 72; ck++) {
                ulonglong2 va = *(const ulonglong2*)(vbase + ck * 32);      // px pairs 0,1
                ulonglong2 vb = *(const ulonglong2*)(vbase + ck * 32 + 4);  // px pairs 2,3
                float4 wv = *(const float4*)(wbaseP + ck * NO);
                unsigned long long w0 = dup2(wv.x), w1 = dup2(wv.y);
                unsigned long long w2 = dup2(wv.z), w3 = dup2(wv.w);
                fma2(acc[0][0], va.x, w0); fma2(acc[0][1], va.x, w1);
                fma2(acc[0][2], va.x, w2); fma2(acc[0][3], va.x, w3);
                fma2(acc[1][0], va.y, w0); fma2(acc[1][1], va.y, w1);
                fma2(acc[1][2], va.y, w2); fma2(acc[1][3], va.y, w3);
                fma2(acc[2][0], vb.x, w0); fma2(acc[2][1], vb.x, w1);
                fma2(acc[2][2], vb.x, w2); fma2(acc[2][3], vb.x, w3);
                fma2(acc[3][0], vb.y, w0); fma2(acc[3][1], vb.y, w1);
                fma2(acc[3][2], vb.y, w2); fma2(acc[3][3], vb.y, w3);
            }
        }
        __syncthreads();   // vals consumed; reuse as partial buffer

        // ---- partial store: region per ckg, layout [px][66] ----
        float* reg = vals + ckg * 2112;
#pragma unroll
        for (int pp = 0; pp < 4; pp++) {
            int px0 = pxg * 8 + pp * 2;
#pragma unroll
            for (int j = 0; j < 4; j++) {
                float lo, hi;
                unpack2(acc[pp][j], lo, hi);
                reg[px0 * 66 + o_base + j] = lo;
                reg[(px0 + 1) * 66 + o_base + j] = hi;
            }
        }
        __syncthreads();

        // ---- final reduce + store: lane = px (coalesced), warp -> 4 o ----
#pragma unroll
        for (int j = 0; j < 4; j++) {
            int o = wi * 4 + j;
            float s = __ldg(&bias[o]);
#pragma unroll
            for (int g = 0; g < 8; g++) s += vals[g * 2112 + l * 66 + o];
            out[((b * NO + o) * NH + h) * NW + wbase + l] = s;
        }
    }
}

// ---------------------------------------------------------------------------
extern "C" void kernel_launch(void* const* d_in, const int* in_sizes, int n_in,
                              void* d_out, int out_size) {
    const float* x      = (const float*)d_in[0];
    const float* weight = (const float*)d_in[1];
    const float* bias   = (const float*)d_in[2];
    const float* offw   = (const float*)d_in[3];
    const float* offb   = (const float*)d_in[4];
    float* out = (float*)d_out;

    (void)in_sizes; (void)n_in; (void)out_size;

    cudaFuncSetAttribute(deform_kernel,
                         cudaFuncAttributeMaxDynamicSharedMemorySize, SMEM_BYTES);

    transpose_w_kernel<<<(NO * NCK + 255) / 256, 256>>>(weight);
    offsets_kernel<<<dim3(NH, NB), 128>>>(x, offw, offb);
    deform_kernel<<<152, 512, SMEM_BYTES>>>(x, bias, out);
}